// round 6
// baseline (speedup 1.0000x reference)
#include <cuda_runtime.h>

#define NN 100000
#define NE 1000000
#define CH 64
#define NG 1024

// ---- scratch (static __device__ — no allocations allowed) ----
__device__ int   g_is64;                 // 1 if index arrays are int64, 0 if int32
__device__ int   g_degc[NN];
__device__ float g_dinv[NN];
__device__ int   g_rowptr[NN + 1];
__device__ int   g_cursor[NN];
__device__ int   g_bsum[128];
__device__ int   g_boff[128];
__device__ int   g_csrc[NE];
__device__ float g_y[(size_t)NN * CH];   // (h @ W) * dinv, per layer
__device__ float g_h[(size_t)NN * CH];   // hidden activations
__device__ float g_gsum[NG];
__device__ int   g_gcnt[NG];

__device__ __forceinline__ int load_id(const void* p, long long i, int is64) {
    if (is64) return (int)((const long long*)p)[i];
    return ((const int*)p)[i];
}

// ---- dtype detection: int64 little-endian => odd int32 words are zero ----
__global__ void k_detect(const int* __restrict__ ei32) {
    if (blockIdx.x == 0 && threadIdx.x == 0) {
        int zeros = 0;
        for (int i = 0; i < 256; i++)          // words 1,3,...,511: safe for int32 too
            if (ei32[2 * i + 1] == 0) zeros++;
        g_is64 = (zeros >= 200) ? 1 : 0;
    }
}

// ---- init / degree / graph counts ----
__global__ void k_zero() {
    int i = blockIdx.x * blockDim.x + threadIdx.x;
    if (i < NN) g_degc[i] = 0;
    if (i < NG) { g_gsum[i] = 0.f; g_gcnt[i] = 0; }
}

__global__ void k_deg(const void* __restrict__ ei) {
    int e = blockIdx.x * blockDim.x + threadIdx.x;
    if (e < NE) {
        int dst = load_id(ei, (long long)NE + e, g_is64);
        if ((unsigned)dst < NN) atomicAdd(&g_degc[dst], 1);
    }
}

__global__ void k_gcnt(const void* __restrict__ batch) {
    int i = blockIdx.x * blockDim.x + threadIdx.x;
    if (i < NN) {
        int g = load_id(batch, i, g_is64);
        if ((unsigned)g < NG) {
            unsigned act = __activemask();
            unsigned m = __match_any_sync(act, g);
            int leader = __ffs(m) - 1;
            if ((int)(threadIdx.x & 31) == leader) atomicAdd(&g_gcnt[g], __popc(m));
        }
    }
}

// ---- 3-kernel exclusive scan of degree -> rowptr ----
__global__ void k_scan1() {
    __shared__ int tmp[1024];
    int t = threadIdx.x;
    int i = blockIdx.x * 1024 + t;
    int v = (i < NN) ? g_degc[i] : 0;
    tmp[t] = v; __syncthreads();
    for (int off = 1; off < 1024; off <<= 1) {
        int a = (t >= off) ? tmp[t - off] : 0;
        __syncthreads();
        tmp[t] += a;
        __syncthreads();
    }
    if (i < NN) g_rowptr[i] = tmp[t] - v;          // exclusive within block
    if (t == 1023) g_bsum[blockIdx.x] = tmp[t];     // block total
}

__global__ void k_scan2() {
    __shared__ int tmp[128];
    const int B = (NN + 1023) / 1024;               // 98
    int t = threadIdx.x;
    int v = (t < B) ? g_bsum[t] : 0;
    tmp[t] = v; __syncthreads();
    for (int off = 1; off < 128; off <<= 1) {
        int a = (t >= off) ? tmp[t - off] : 0;
        __syncthreads();
        tmp[t] += a;
        __syncthreads();
    }
    if (t < B) g_boff[t] = tmp[t] - v;
}

__global__ void k_scan3() {
    int i = blockIdx.x * blockDim.x + threadIdx.x;
    if (i < NN) {
        int rp = g_rowptr[i] + g_boff[i >> 10];
        g_rowptr[i] = rp;
        g_cursor[i] = rp;
        g_dinv[i] = rsqrtf((float)g_degc[i] + 1.0f);
    }
    if (i == 0) g_rowptr[NN] = NE;
}

__global__ void k_csr(const void* __restrict__ ei) {
    int e = blockIdx.x * blockDim.x + threadIdx.x;
    if (e < NE) {
        int is64 = g_is64;
        int src = load_id(ei, e, is64);
        int dst = load_id(ei, (long long)NE + e, is64);
        if ((unsigned)dst < NN && (unsigned)src < NN) {
            int p = atomicAdd(&g_cursor[dst], 1);
            if ((unsigned)p < NE) g_csrc[p] = src;
        }
    }
}

// ---- GEMM: y[i,:] = (in[i,:] @ W) * dinv[i]   (in = x input or g_h) ----
// block = 256 threads = 64 row-groups x 4 col-segs; each thread: 4 rows x 16 cols
__global__ void __launch_bounds__(256) k_gemm(const float* __restrict__ xin,
                                              const float* __restrict__ W,
                                              int use_h) {
    __shared__ __align__(16) float Ws[CH * CH];
    const float* in = use_h ? (const float*)g_h : xin;
    int tid = threadIdx.x;
    {
        const float4* W4 = (const float4*)W;
        float4* Ws4 = (float4*)Ws;
        for (int i = tid; i < CH * CH / 4; i += 256) Ws4[i] = W4[i];
    }
    __syncthreads();

    int seg = tid & 3;           // col segment: cols [seg*16, seg*16+16)
    int rg  = tid >> 2;          // row group 0..63
    int row0 = blockIdx.x * 256 + rg * 4;

    float4 acc[4][4];
#pragma unroll
    for (int r = 0; r < 4; r++)
#pragma unroll
        for (int c = 0; c < 4; c++) acc[r][c] = make_float4(0.f, 0.f, 0.f, 0.f);

    int rl[4];
#pragma unroll
    for (int r = 0; r < 4; r++) {
        int rr = row0 + r;
        rl[r] = (rr < NN) ? rr : (NN - 1);
    }

    const float4* Ws4 = (const float4*)Ws;
    for (int k0 = 0; k0 < CH; k0 += 4) {
        float4 xv[4];
#pragma unroll
        for (int r = 0; r < 4; r++)
            xv[r] = *(const float4*)(in + (size_t)rl[r] * CH + k0);
#pragma unroll
        for (int kk = 0; kk < 4; kk++) {
            float4 wv[4];
#pragma unroll
            for (int c = 0; c < 4; c++)
                wv[c] = Ws4[(k0 + kk) * (CH / 4) + seg * 4 + c];
#pragma unroll
            for (int r = 0; r < 4; r++) {
                float xk = (kk == 0) ? xv[r].x : (kk == 1) ? xv[r].y
                         : (kk == 2) ? xv[r].z : xv[r].w;
#pragma unroll
                for (int c = 0; c < 4; c++) {
                    acc[r][c].x = fmaf(xk, wv[c].x, acc[r][c].x);
                    acc[r][c].y = fmaf(xk, wv[c].y, acc[r][c].y);
                    acc[r][c].z = fmaf(xk, wv[c].z, acc[r][c].z);
                    acc[r][c].w = fmaf(xk, wv[c].w, acc[r][c].w);
                }
            }
        }
    }

#pragma unroll
    for (int r = 0; r < 4; r++) {
        int rr = row0 + r;
        if (rr < NN) {
            float d = g_dinv[rr];
            float4* o = (float4*)(g_y + (size_t)rr * CH + seg * 16);
#pragma unroll
            for (int c = 0; c < 4; c++) {
                float4 v = acc[r][c];
                v.x *= d; v.y *= d; v.z *= d; v.w *= d;
                o[c] = v;
            }
        }
    }
}

// ---- layer-1 aggregate: h[i] = relu(dinv[i]*(sum_in y[src] + y[i]) + b1) ----
// one warp per node, each lane owns 2 channels (float2)
__global__ void k_agg1(const float* __restrict__ b) {
    int i = (blockIdx.x * blockDim.x + threadIdx.x) >> 5;
    int lane = threadIdx.x & 31;
    if (i >= NN) return;

    const float2* __restrict__ y2 = (const float2*)g_y;
    float2 acc = __ldg(&y2[(size_t)i * (CH / 2) + lane]);  // self loop
    int e = g_rowptr[i], end = g_rowptr[i + 1];
    for (; e + 4 <= end; e += 4) {
        int s0 = g_csrc[e], s1 = g_csrc[e + 1], s2 = g_csrc[e + 2], s3 = g_csrc[e + 3];
        float2 a0 = __ldg(&y2[(size_t)s0 * (CH / 2) + lane]);
        float2 a1 = __ldg(&y2[(size_t)s1 * (CH / 2) + lane]);
        float2 a2 = __ldg(&y2[(size_t)s2 * (CH / 2) + lane]);
        float2 a3 = __ldg(&y2[(size_t)s3 * (CH / 2) + lane]);
        acc.x += a0.x + a1.x + a2.x + a3.x;
        acc.y += a0.y + a1.y + a2.y + a3.y;
    }
    for (; e < end; e++) {
        int s = g_csrc[e];
        float2 a = __ldg(&y2[(size_t)s * (CH / 2) + lane]);
        acc.x += a.x; acc.y += a.y;
    }
    float d = g_dinv[i];
    float2 bb = ((const float2*)b)[lane];
    float2 h;
    h.x = fmaxf(fmaf(d, acc.x, bb.x), 0.f);
    h.y = fmaxf(fmaf(d, acc.y, bb.y), 0.f);
    ((float2*)(g_h + (size_t)i * CH))[lane] = h;
}

// ---- layer-2 aggregate fused with Wout dot + graph-sum atomic ----
__global__ void k_agg2(const float* __restrict__ b,
                       const float* __restrict__ Wout,
                       const void* __restrict__ batch) {
    int i = (blockIdx.x * blockDim.x + threadIdx.x) >> 5;
    int lane = threadIdx.x & 31;
    if (i >= NN) return;

    const float2* __restrict__ y2 = (const float2*)g_y;
    float2 acc = __ldg(&y2[(size_t)i * (CH / 2) + lane]);
    int e = g_rowptr[i], end = g_rowptr[i + 1];
    for (; e + 4 <= end; e += 4) {
        int s0 = g_csrc[e], s1 = g_csrc[e + 1], s2 = g_csrc[e + 2], s3 = g_csrc[e + 3];
        float2 a0 = __ldg(&y2[(size_t)s0 * (CH / 2) + lane]);
        float2 a1 = __ldg(&y2[(size_t)s1 * (CH / 2) + lane]);
        float2 a2 = __ldg(&y2[(size_t)s2 * (CH / 2) + lane]);
        float2 a3 = __ldg(&y2[(size_t)s3 * (CH / 2) + lane]);
        acc.x += a0.x + a1.x + a2.x + a3.x;
        acc.y += a0.y + a1.y + a2.y + a3.y;
    }
    for (; e < end; e++) {
        int s = g_csrc[e];
        float2 a = __ldg(&y2[(size_t)s * (CH / 2) + lane]);
        acc.x += a.x; acc.y += a.y;
    }
    float d = g_dinv[i];
    float2 bb = ((const float2*)b)[lane];
    float hx = fmaxf(fmaf(d, acc.x, bb.x), 0.f);
    float hy = fmaxf(fmaf(d, acc.y, bb.y), 0.f);
    float2 wo = ((const float2*)Wout)[lane];
    float s = hx * wo.x + hy * wo.y;
#pragma unroll
    for (int off = 16; off; off >>= 1) s += __shfl_xor_sync(0xffffffffu, s, off);
    if (lane == 0) {
        int g = load_id(batch, i, g_is64);
        if ((unsigned)g < NG) atomicAdd(&g_gsum[g], s);
    }
}

__global__ void k_out(const float* __restrict__ bout, float* __restrict__ out) {
    int g = blockIdx.x * blockDim.x + threadIdx.x;
    if (g < NG) out[g] = g_gsum[g] / fmaxf((float)g_gcnt[g], 1.f) + bout[0];
}

extern "C" void kernel_launch(void* const* d_in, const int* in_sizes, int n_in,
                              void* d_out, int out_size) {
    const float* x     = (const float*)d_in[0];
    const void*  ei    = d_in[1];
    const void*  batch = d_in[2];
    const float* W1    = (const float*)d_in[3];
    const float* b1    = (const float*)d_in[4];
    const float* W2    = (const float*)d_in[5];
    const float* b2    = (const float*)d_in[6];
    const float* Wout  = (const float*)d_in[7];
    const float* bout  = (const float*)d_in[8];
    float*       out   = (float*)d_out;

    (void)in_sizes; (void)n_in; (void)out_size;

    k_detect<<<1, 32>>>((const int*)ei);
    k_zero <<<(NN + 255) / 256, 256>>>();
    k_deg  <<<(NE + 255) / 256, 256>>>(ei);
    k_gcnt <<<(NN + 255) / 256, 256>>>(batch);
    k_scan1<<<(NN + 1023) / 1024, 1024>>>();
    k_scan2<<<1, 128>>>();
    k_scan3<<<(NN + 255) / 256, 256>>>();
    k_csr  <<<(NE + 255) / 256, 256>>>(ei);

    // layer 1
    k_gemm <<<(NN + 255) / 256, 256>>>(x, W1, 0);
    k_agg1 <<<(NN * 32 + 255) / 256, 256>>>(b1);
    // layer 2 (+ fused pool/head)
    k_gemm <<<(NN + 255) / 256, 256>>>(x, W2, 1);
    k_agg2 <<<(NN * 32 + 255) / 256, 256>>>(b2, Wout, batch);

    k_out  <<<(NG + 255) / 256, 256>>>(bout, out);
}

// round 8
// speedup vs baseline: 1.2526x; 1.2526x over previous
#include <cuda_runtime.h>

#define NN 100000
#define NE 1000000
#define CH 64
#define NG 1024

typedef unsigned long long ull;
typedef long long ll;

// ---- scratch (static __device__ — no allocations allowed) ----
__device__ int   g_is64;                 // 1 if index arrays are int64, 0 if int32
__device__ int   g_degc[NN];
__device__ float g_dinv[NN];
__device__ int   g_rowptr[NN + 1];
__device__ int   g_cursor[NN];
__device__ int   g_bsum[128];
__device__ int   g_boff[128];
__device__ int   g_csrc[NE];
__device__ float g_y[(size_t)NN * CH];   // (h @ W) * dinv, per layer
__device__ float g_h[(size_t)NN * CH];   // hidden activations
__device__ float g_gsum[NG];
__device__ int   g_gcnt[NG];

// ---- packed fp32x2 helpers (sm_100+) ----
__device__ __forceinline__ ull ffma2(ull a, ull b, ull c) {
    ull d; asm("fma.rn.f32x2 %0, %1, %2, %3;" : "=l"(d) : "l"(a), "l"(b), "l"(c));
    return d;
}
__device__ __forceinline__ ull fadd2(ull a, ull b) {
    ull d; asm("add.rn.f32x2 %0, %1, %2;" : "=l"(d) : "l"(a), "l"(b));
    return d;
}
__device__ __forceinline__ ull fmul2(ull a, ull b) {
    ull d; asm("mul.rn.f32x2 %0, %1, %2;" : "=l"(d) : "l"(a), "l"(b));
    return d;
}
__device__ __forceinline__ ull bcast2(float x) {
    ull r; asm("mov.b64 %0, {%1, %1};" : "=l"(r) : "f"(x));
    return r;
}
__device__ __forceinline__ float2 unpack2(ull v) {
    float2 f; asm("mov.b64 {%0, %1}, %2;" : "=f"(f.x), "=f"(f.y) : "l"(v));
    return f;
}

__device__ __forceinline__ int load_id(const void* p, ll i, int is64) {
    if (is64) return (int)((const ll*)p)[i];
    return ((const int*)p)[i];
}

// ---- fused: dtype detection + zero init ----
__global__ void k_init(const int* __restrict__ ei32) {
    int i = blockIdx.x * blockDim.x + threadIdx.x;
    if (i < NN) g_degc[i] = 0;
    if (i < NG) { g_gsum[i] = 0.f; g_gcnt[i] = 0; }
    if (blockIdx.x == 0) {
        // int64 little-endian => odd int32 words are the zero upper halves
        int z = (ei32[2 * threadIdx.x + 1] == 0) ? 1 : 0;
        int tot = __syncthreads_count(z);
        if (threadIdx.x == 0) g_is64 = (tot >= 200) ? 1 : 0;
    }
}

// ---- fused: degree histogram (2 edges/thread, vector loads) + graph counts ----
__global__ void k_degcnt(const void* __restrict__ ei, const void* __restrict__ batch) {
    int t = blockIdx.x * blockDim.x + threadIdx.x;
    int is64 = g_is64;
    int e = t * 2;
    if (e < NE) {
        int d0, d1;
        if (is64) {
            longlong2 v = __ldg(&((const longlong2*)((const ll*)ei + NE))[t]);
            d0 = (int)v.x; d1 = (int)v.y;
        } else {
            int2 v = __ldg(&((const int2*)((const int*)ei + NE))[t]);
            d0 = v.x; d1 = v.y;
        }
        if ((unsigned)d0 < NN) atomicAdd(&g_degc[d0], 1);
        if (e + 1 < NE && (unsigned)d1 < NN) atomicAdd(&g_degc[d1], 1);
    }
    if (t < NN) {
        int g = load_id(batch, t, is64);
        if ((unsigned)g < NG) {
            unsigned act = __activemask();
            unsigned m = __match_any_sync(act, g);
            int leader = __ffs(m) - 1;
            if ((int)(threadIdx.x & 31) == leader) atomicAdd(&g_gcnt[g], __popc(m));
        }
    }
}

// ---- 3-kernel exclusive scan of degree -> rowptr ----
__global__ void k_scan1() {
    __shared__ int tmp[1024];
    int t = threadIdx.x;
    int i = blockIdx.x * 1024 + t;
    int v = (i < NN) ? g_degc[i] : 0;
    tmp[t] = v; __syncthreads();
    for (int off = 1; off < 1024; off <<= 1) {
        int a = (t >= off) ? tmp[t - off] : 0;
        __syncthreads();
        tmp[t] += a;
        __syncthreads();
    }
    if (i < NN) g_rowptr[i] = tmp[t] - v;          // exclusive within block
    if (t == 1023) g_bsum[blockIdx.x] = tmp[t];     // block total
}

__global__ void k_scan2() {
    __shared__ int tmp[128];
    const int B = (NN + 1023) / 1024;               // 98
    int t = threadIdx.x;
    int v = (t < B) ? g_bsum[t] : 0;
    tmp[t] = v; __syncthreads();
    for (int off = 1; off < 128; off <<= 1) {
        int a = (t >= off) ? tmp[t - off] : 0;
        __syncthreads();
        tmp[t] += a;
        __syncthreads();
    }
    if (t < B) g_boff[t] = tmp[t] - v;
}

__global__ void k_scan3() {
    int i = blockIdx.x * blockDim.x + threadIdx.x;
    if (i < NN) {
        int rp = g_rowptr[i] + g_boff[i >> 10];
        g_rowptr[i] = rp;
        g_cursor[i] = rp;
        g_dinv[i] = rsqrtf((float)g_degc[i] + 1.0f);
    }
    if (i == 0) g_rowptr[NN] = NE;
}

// ---- CSR fill: 2 edges/thread, vectorized index loads ----
__global__ void k_csr(const void* __restrict__ ei) {
    int t = blockIdx.x * blockDim.x + threadIdx.x;
    int e = t * 2;
    if (e >= NE) return;
    int is64 = g_is64;
    int s0, s1, d0, d1;
    if (is64) {
        longlong2 sv = __ldg(&((const longlong2*)ei)[t]);
        longlong2 dv = __ldg(&((const longlong2*)((const ll*)ei + NE))[t]);
        s0 = (int)sv.x; s1 = (int)sv.y; d0 = (int)dv.x; d1 = (int)dv.y;
    } else {
        int2 sv = __ldg(&((const int2*)ei)[t]);
        int2 dv = __ldg(&((const int2*)((const int*)ei + NE))[t]);
        s0 = sv.x; s1 = sv.y; d0 = dv.x; d1 = dv.y;
    }
    if ((unsigned)d0 < NN && (unsigned)s0 < NN) {
        int p = atomicAdd(&g_cursor[d0], 1);
        if ((unsigned)p < NE) g_csrc[p] = s0;
    }
    if (e + 1 < NE && (unsigned)d1 < NN && (unsigned)s1 < NN) {
        int p = atomicAdd(&g_cursor[d1], 1);
        if ((unsigned)p < NE) g_csrc[p] = s1;
    }
}

// ---- GEMM: y[i,:] = (in[i,:] @ W) * dinv[i], packed fp32x2 FFMA ----
// block = 256 threads = 32 row-groups x 8 col-groups; each thread: 8 rows x 8 cols
__global__ void __launch_bounds__(256) k_gemm(const float* __restrict__ xin,
                                              const float* __restrict__ W,
                                              int use_h) {
    __shared__ __align__(16) float Ws[CH * CH];
    const float* in = use_h ? (const float*)g_h : xin;
    int tid = threadIdx.x;
    for (int i = tid; i < CH * CH / 4; i += 256)
        ((float4*)Ws)[i] = ((const float4*)W)[i];
    __syncthreads();

    int cg = tid & 7;            // col group: cols [cg*8, cg*8+8)
    int rg = tid >> 3;           // row group 0..31
    int row0 = blockIdx.x * 256 + rg * 8;

    ull acc[8][4];
#pragma unroll
    for (int r = 0; r < 8; r++)
#pragma unroll
        for (int c = 0; c < 4; c++) acc[r][c] = 0ull;

    int rl[8];
#pragma unroll
    for (int r = 0; r < 8; r++) {
        int rr = row0 + r;
        rl[r] = (rr < NN) ? rr : (NN - 1);
    }

    const ull* Ws2 = (const ull*)Ws;
    for (int k0 = 0; k0 < CH; k0 += 4) {
        float4 xv[8];
#pragma unroll
        for (int r = 0; r < 8; r++)
            xv[r] = __ldg((const float4*)(in + (size_t)rl[r] * CH + k0));
#pragma unroll
        for (int kk = 0; kk < 4; kk++) {
            ull wv[4];
#pragma unroll
            for (int c = 0; c < 4; c++)
                wv[c] = Ws2[(k0 + kk) * (CH / 2) + cg * 4 + c];
#pragma unroll
            for (int r = 0; r < 8; r++) {
                float xk = (kk == 0) ? xv[r].x : (kk == 1) ? xv[r].y
                         : (kk == 2) ? xv[r].z : xv[r].w;
                ull xk2 = bcast2(xk);
#pragma unroll
                for (int c = 0; c < 4; c++)
                    acc[r][c] = ffma2(xk2, wv[c], acc[r][c]);
            }
        }
    }

#pragma unroll
    for (int r = 0; r < 8; r++) {
        int rr = row0 + r;
        if (rr < NN) {
            ull d2 = bcast2(g_dinv[rr]);
            ull* o = (ull*)(g_y + (size_t)rr * CH + cg * 8);
#pragma unroll
            for (int c = 0; c < 4; c++)
                o[c] = fmul2(acc[r][c], d2);
        }
    }
}

// ---- layer-1 aggregate: h[i] = relu(dinv[i]*(sum_in y[src] + y[i]) + b1) ----
// one warp per node, each lane owns 2 channels (packed f32x2)
__global__ void k_agg1(const float* __restrict__ b) {
    int i = (blockIdx.x * blockDim.x + threadIdx.x) >> 5;
    int lane = threadIdx.x & 31;
    if (i >= NN) return;

    const ull* __restrict__ y2 = (const ull*)g_y;
    ull acc = __ldg(&y2[(size_t)i * (CH / 2) + lane]);  // self loop
    int e = g_rowptr[i], end = g_rowptr[i + 1];
    for (; e + 4 <= end; e += 4) {
        int s0 = g_csrc[e], s1 = g_csrc[e + 1], s2 = g_csrc[e + 2], s3 = g_csrc[e + 3];
        ull a0 = __ldg(&y2[(size_t)s0 * (CH / 2) + lane]);
        ull a1 = __ldg(&y2[(size_t)s1 * (CH / 2) + lane]);
        ull a2 = __ldg(&y2[(size_t)s2 * (CH / 2) + lane]);
        ull a3 = __ldg(&y2[(size_t)s3 * (CH / 2) + lane]);
        acc = fadd2(acc, fadd2(fadd2(a0, a1), fadd2(a2, a3)));
    }
    for (; e < end; e++) {
        int s = g_csrc[e];
        acc = fadd2(acc, __ldg(&y2[(size_t)s * (CH / 2) + lane]));
    }
    float d = g_dinv[i];
    float2 av = unpack2(acc);
    float2 bb = ((const float2*)b)[lane];
    float2 h;
    h.x = fmaxf(fmaf(d, av.x, bb.x), 0.f);
    h.y = fmaxf(fmaf(d, av.y, bb.y), 0.f);
    ((float2*)(g_h + (size_t)i * CH))[lane] = h;
}

// ---- layer-2 aggregate fused with Wout dot + graph-sum atomic ----
__global__ void k_agg2(const float* __restrict__ b,
                       const float* __restrict__ Wout,
                       const void* __restrict__ batch) {
    int i = (blockIdx.x * blockDim.x + threadIdx.x) >> 5;
    int lane = threadIdx.x & 31;
    if (i >= NN) return;

    const ull* __restrict__ y2 = (const ull*)g_y;
    ull acc = __ldg(&y2[(size_t)i * (CH / 2) + lane]);
    int e = g_rowptr[i], end = g_rowptr[i + 1];
    for (; e + 4 <= end; e += 4) {
        int s0 = g_csrc[e], s1 = g_csrc[e + 1], s2 = g_csrc[e + 2], s3 = g_csrc[e + 3];
        ull a0 = __ldg(&y2[(size_t)s0 * (CH / 2) + lane]);
        ull a1 = __ldg(&y2[(size_t)s1 * (CH / 2) + lane]);
        ull a2 = __ldg(&y2[(size_t)s2 * (CH / 2) + lane]);
        ull a3 = __ldg(&y2[(size_t)s3 * (CH / 2) + lane]);
        acc = fadd2(acc, fadd2(fadd2(a0, a1), fadd2(a2, a3)));
    }
    for (; e < end; e++) {
        int s = g_csrc[e];
        acc = fadd2(acc, __ldg(&y2[(size_t)s * (CH / 2) + lane]));
    }
    float d = g_dinv[i];
    float2 av = unpack2(acc);
    float2 bb = ((const float2*)b)[lane];
    float hx = fmaxf(fmaf(d, av.x, bb.x), 0.f);
    float hy = fmaxf(fmaf(d, av.y, bb.y), 0.f);
    float2 wo = ((const float2*)Wout)[lane];
    float s = hx * wo.x + hy * wo.y;
#pragma unroll
    for (int off = 16; off; off >>= 1) s += __shfl_xor_sync(0xffffffffu, s, off);
    if (lane == 0) {
        int g = load_id(batch, i, g_is64);
        if ((unsigned)g < NG) atomicAdd(&g_gsum[g], s);
    }
}

__global__ void k_out(const float* __restrict__ bout, float* __restrict__ out) {
    int g = blockIdx.x * blockDim.x + threadIdx.x;
    if (g < NG) out[g] = g_gsum[g] / fmaxf((float)g_gcnt[g], 1.f) + bout[0];
}

extern "C" void kernel_launch(void* const* d_in, const int* in_sizes, int n_in,
                              void* d_out, int out_size) {
    const float* x     = (const float*)d_in[0];
    const void*  ei    = d_in[1];
    const void*  batch = d_in[2];
    const float* W1    = (const float*)d_in[3];
    const float* b1    = (const float*)d_in[4];
    const float* W2    = (const float*)d_in[5];
    const float* b2    = (const float*)d_in[6];
    const float* Wout  = (const float*)d_in[7];
    const float* bout  = (const float*)d_in[8];
    float*       out   = (float*)d_out;

    (void)in_sizes; (void)n_in; (void)out_size;

    k_init  <<<(NN + 255) / 256, 256>>>((const int*)ei);
    k_degcnt<<<(NE / 2 + 255) / 256, 256>>>(ei, batch);
    k_scan1 <<<(NN + 1023) / 1024, 1024>>>();
    k_scan2 <<<1, 128>>>();
    k_scan3 <<<(NN + 255) / 256, 256>>>();
    k_csr   <<<(NE / 2 + 255) / 256, 256>>>(ei);

    // layer 1
    k_gemm  <<<(NN + 255) / 256, 256>>>(x, W1, 0);
    k_agg1  <<<(NN * 32 + 255) / 256, 256>>>(b1);
    // layer 2 (+ fused pool/head)
    k_gemm  <<<(NN + 255) / 256, 256>>>(x, W2, 1);
    k_agg2  <<<(NN * 32 + 255) / 256, 256>>>(b2, Wout, batch);

    k_out   <<<(NG + 255) / 256, 256>>>(bout, out);
}

// round 10
// speedup vs baseline: 1.4176x; 1.1317x over previous
#include <cuda_runtime.h>

#define NN 100000
#define NE 1000000
#define CH 64
#define NG 1024

typedef unsigned long long ull;
typedef long long ll;

// ---- scratch (static __device__ — no allocations allowed) ----
__device__ int      g_is64;              // 1 if index arrays are int64, 0 if int32
__device__ int      g_degc[NN];
__device__ float    g_dinv[NN];
__device__ float    g_ginv[NG];          // 1/max(graph count,1)
__device__ int      g_rowptr[NN + 1];
__device__ int      g_cursor[NN];
__device__ int      g_bsum[128];
__device__ int      g_csrc[NE];
__device__ unsigned g_yb[(size_t)NN * (CH / 2)];  // (h @ W) * dinv, bf16x2 packed
__device__ float    g_h[(size_t)NN * CH];         // hidden activations (fp32)
__device__ int      g_gcnt[NG];

// ---- packed fp32x2 helpers (sm_100+) ----
__device__ __forceinline__ ull ffma2(ull a, ull b, ull c) {
    ull d; asm("fma.rn.f32x2 %0, %1, %2, %3;" : "=l"(d) : "l"(a), "l"(b), "l"(c));
    return d;
}
__device__ __forceinline__ ull fmul2(ull a, ull b) {
    ull d; asm("mul.rn.f32x2 %0, %1, %2;" : "=l"(d) : "l"(a), "l"(b));
    return d;
}
__device__ __forceinline__ ull bcast2(float x) {
    ull r; asm("mov.b64 %0, {%1, %1};" : "=l"(r) : "f"(x));
    return r;
}
__device__ __forceinline__ float2 unpack2(ull v) {
    float2 f; asm("mov.b64 {%0, %1}, %2;" : "=f"(f.x), "=f"(f.y) : "l"(v));
    return f;
}
// pack two fp32 -> bf16x2 (lo in low half), round-to-nearest
__device__ __forceinline__ unsigned pk_bf16x2(float lo, float hi) {
    unsigned r; asm("cvt.rn.bf16x2.f32 %0, %1, %2;" : "=r"(r) : "f"(hi), "f"(lo));
    return r;
}

__device__ __forceinline__ int load_id(const void* p, ll i, int is64) {
    if (is64) return (int)((const ll*)p)[i];
    return ((const int*)p)[i];
}

// ---- fused: dtype detection + zero init + out prefill with bias ----
__global__ void k_init(const int* __restrict__ ei32, const float* __restrict__ bout,
                       float* __restrict__ out) {
    int i = blockIdx.x * blockDim.x + threadIdx.x;
    if (i < NN) g_degc[i] = 0;
    if (i < NG) { g_gcnt[i] = 0; out[i] = bout[0]; }
    if (blockIdx.x == 0) {
        // int64 little-endian => odd int32 words are the zero upper halves
        int z = (ei32[2 * threadIdx.x + 1] == 0) ? 1 : 0;
        int tot = __syncthreads_count(z);
        if (threadIdx.x == 0) g_is64 = (tot >= 200) ? 1 : 0;
    }
}

// ---- fused: degree histogram (2 edges/thread, vector loads) + graph counts ----
__global__ void k_degcnt(const void* __restrict__ ei, const void* __restrict__ batch) {
    int t = blockIdx.x * blockDim.x + threadIdx.x;
    int is64 = g_is64;
    int e = t * 2;
    if (e < NE) {
        int d0, d1;
        if (is64) {
            longlong2 v = __ldg(&((const longlong2*)((const ll*)ei + NE))[t]);
            d0 = (int)v.x; d1 = (int)v.y;
        } else {
            int2 v = __ldg(&((const int2*)((const int*)ei + NE))[t]);
            d0 = v.x; d1 = v.y;
        }
        if ((unsigned)d0 < NN) atomicAdd(&g_degc[d0], 1);
        if (e + 1 < NE && (unsigned)d1 < NN) atomicAdd(&g_degc[d1], 1);
    }
    if (t < NN) {
        int g = load_id(batch, t, is64);
        if ((unsigned)g < NG) {
            unsigned act = __activemask();
            unsigned m = __match_any_sync(act, g);
            int leader = __ffs(m) - 1;
            if ((int)(threadIdx.x & 31) == leader) atomicAdd(&g_gcnt[g], __popc(m));
        }
    }
}

// ---- scan stage 1: block-local exclusive scan of degree ----
__global__ void k_scan1() {
    __shared__ int tmp[1024];
    int t = threadIdx.x;
    int i = blockIdx.x * 1024 + t;
    int v = (i < NN) ? g_degc[i] : 0;
    tmp[t] = v; __syncthreads();
    for (int off = 1; off < 1024; off <<= 1) {
        int a = (t >= off) ? tmp[t - off] : 0;
        __syncthreads();
        tmp[t] += a;
        __syncthreads();
    }
    if (i < NN) g_rowptr[i] = tmp[t] - v;          // exclusive within block
    if (t == 1023) g_bsum[blockIdx.x] = tmp[t];     // block total
}

// ---- scan stage 2 fused with apply + dinv + cursor + ginv ----
__global__ void k_scanapply() {
    __shared__ int tmp[128];
    const int B = (NN + 1023) / 1024;               // 98
    int t = threadIdx.x;                            // 256 threads
    if (t < 128) tmp[t] = (t < B) ? g_bsum[t] : 0;
    __syncthreads();
    for (int off = 1; off < 128; off <<= 1) {
        int a = 0;
        if (t < 128 && t >= off) a = tmp[t - off];
        __syncthreads();
        if (t < 128) tmp[t] += a;
        __syncthreads();
    }
    if (t < 128) tmp[t] -= (t < B) ? g_bsum[t] : 0;  // -> exclusive
    __syncthreads();

    int i = blockIdx.x * 256 + t;
    if (i < NN) {
        int rp = g_rowptr[i] + tmp[i >> 10];
        g_rowptr[i] = rp;
        g_cursor[i] = rp;
        g_dinv[i] = rsqrtf((float)g_degc[i] + 1.0f);
    }
    if (i < NG) g_ginv[i] = 1.0f / fmaxf((float)g_gcnt[i], 1.f);
    if (i == 0) g_rowptr[NN] = NE;
}

// ---- CSR fill: 2 edges/thread, vectorized index loads ----
__global__ void k_csr(const void* __restrict__ ei) {
    int t = blockIdx.x * blockDim.x + threadIdx.x;
    int e = t * 2;
    if (e >= NE) return;
    int is64 = g_is64;
    int s0, s1, d0, d1;
    if (is64) {
        longlong2 sv = __ldg(&((const longlong2*)ei)[t]);
        longlong2 dv = __ldg(&((const longlong2*)((const ll*)ei + NE))[t]);
        s0 = (int)sv.x; s1 = (int)sv.y; d0 = (int)dv.x; d1 = (int)dv.y;
    } else {
        int2 sv = __ldg(&((const int2*)ei)[t]);
        int2 dv = __ldg(&((const int2*)((const int*)ei + NE))[t]);
        s0 = sv.x; s1 = sv.y; d0 = dv.x; d1 = dv.y;
    }
    if ((unsigned)d0 < NN && (unsigned)s0 < NN) {
        int p = atomicAdd(&g_cursor[d0], 1);
        if ((unsigned)p < NE) g_csrc[p] = s0;
    }
    if (e + 1 < NE && (unsigned)d1 < NN && (unsigned)s1 < NN) {
        int p = atomicAdd(&g_cursor[d1], 1);
        if ((unsigned)p < NE) g_csrc[p] = s1;
    }
}

// ---- GEMM: y[i,:] = (in[i,:] @ W) * dinv[i], packed fp32x2 FFMA, bf16 out ----
// block = 256 threads = 32 row-groups x 8 col-groups; each thread: 8 rows x 8 cols
__global__ void __launch_bounds__(256) k_gemm(const float* __restrict__ xin,
                                              const float* __restrict__ W,
                                              int use_h) {
    __shared__ __align__(16) float Ws[CH * CH];
    const float* in = use_h ? (const float*)g_h : xin;
    int tid = threadIdx.x;
    for (int i = tid; i < CH * CH / 4; i += 256)
        ((float4*)Ws)[i] = ((const float4*)W)[i];
    __syncthreads();

    int cg = tid & 7;            // col group: cols [cg*8, cg*8+8)
    int rg = tid >> 3;           // row group 0..31
    int row0 = blockIdx.x * 256 + rg * 8;

    ull acc[8][4];
#pragma unroll
    for (int r = 0; r < 8; r++)
#pragma unroll
        for (int c = 0; c < 4; c++) acc[r][c] = 0ull;

    int rl[8];
#pragma unroll
    for (int r = 0; r < 8; r++) {
        int rr = row0 + r;
        rl[r] = (rr < NN) ? rr : (NN - 1);
    }

    const ull* Ws2 = (const ull*)Ws;
    for (int k0 = 0; k0 < CH; k0 += 4) {
        float4 xv[8];
#pragma unroll
        for (int r = 0; r < 8; r++)
            xv[r] = __ldg((const float4*)(in + (size_t)rl[r] * CH + k0));
#pragma unroll
        for (int kk = 0; kk < 4; kk++) {
            ull wv[4];
#pragma unroll
            for (int c = 0; c < 4; c++)
                wv[c] = Ws2[(k0 + kk) * (CH / 2) + cg * 4 + c];
#pragma unroll
            for (int r = 0; r < 8; r++) {
                float xk = (kk == 0) ? xv[r].x : (kk == 1) ? xv[r].y
                         : (kk == 2) ? xv[r].z : xv[r].w;
                ull xk2 = bcast2(xk);
#pragma unroll
                for (int c = 0; c < 4; c++)
                    acc[r][c] = ffma2(xk2, wv[c], acc[r][c]);
            }
        }
    }

#pragma unroll
    for (int r = 0; r < 8; r++) {
        int rr = row0 + r;
        if (rr < NN) {
            ull d2 = bcast2(g_dinv[rr]);
            unsigned w[4];
#pragma unroll
            for (int c = 0; c < 4; c++) {
                float2 v = unpack2(fmul2(acc[r][c], d2));
                w[c] = pk_bf16x2(v.x, v.y);
            }
            ((uint4*)(g_yb + (size_t)rr * (CH / 2)))[cg] =
                make_uint4(w[0], w[1], w[2], w[3]);
        }
    }
}

// bf16x2 word -> two fp32 (exact: shift into exponent position)
#define BF2X(w) __uint_as_float((w) << 16)
#define BF2Y(w) __uint_as_float((w) & 0xffff0000u)

// ---- layer-1 aggregate: h[i] = relu(dinv[i]*(sum_in y[src] + y[i]) + b1) ----
// one warp per node, each lane owns 2 channels (one bf16x2 word per edge)
__global__ void k_agg1(const float* __restrict__ b) {
    int i = (blockIdx.x * blockDim.x + threadIdx.x) >> 5;
    int lane = threadIdx.x & 31;
    if (i >= NN) return;

    const unsigned* __restrict__ yb = g_yb;
    unsigned ws = __ldg(&yb[(size_t)i * 32 + lane]);   // self loop
    float ax = BF2X(ws), ay = BF2Y(ws);
    int e = g_rowptr[i], end = g_rowptr[i + 1];
    for (; e + 4 <= end; e += 4) {
        int s0 = g_csrc[e], s1 = g_csrc[e + 1], s2 = g_csrc[e + 2], s3 = g_csrc[e + 3];
        unsigned w0 = __ldg(&yb[(size_t)s0 * 32 + lane]);
        unsigned w1 = __ldg(&yb[(size_t)s1 * 32 + lane]);
        unsigned w2 = __ldg(&yb[(size_t)s2 * 32 + lane]);
        unsigned w3 = __ldg(&yb[(size_t)s3 * 32 + lane]);
        ax += (BF2X(w0) + BF2X(w1)) + (BF2X(w2) + BF2X(w3));
        ay += (BF2Y(w0) + BF2Y(w1)) + (BF2Y(w2) + BF2Y(w3));
    }
    for (; e < end; e++) {
        int s = g_csrc[e];
        unsigned w = __ldg(&yb[(size_t)s * 32 + lane]);
        ax += BF2X(w); ay += BF2Y(w);
    }
    float d = g_dinv[i];
    float2 bb = ((const float2*)b)[lane];
    float2 h;
    h.x = fmaxf(fmaf(d, ax, bb.x), 0.f);
    h.y = fmaxf(fmaf(d, ay, bb.y), 0.f);
    ((float2*)(g_h + (size_t)i * CH))[lane] = h;
}

// ---- layer-2 aggregate fused with Wout dot + mean-pool atomic into out ----
__global__ void k_agg2(const float* __restrict__ b,
                       const float* __restrict__ Wout,
                       const void* __restrict__ batch,
                       float* __restrict__ out) {
    int i = (blockIdx.x * blockDim.x + threadIdx.x) >> 5;
    int lane = threadIdx.x & 31;
    if (i >= NN) return;

    const unsigned* __restrict__ yb = g_yb;
    unsigned ws = __ldg(&yb[(size_t)i * 32 + lane]);
    float ax = BF2X(ws), ay = BF2Y(ws);
    int e = g_rowptr[i], end = g_rowptr[i + 1];
    for (; e + 4 <= end; e += 4) {
        int s0 = g_csrc[e], s1 = g_csrc[e + 1], s2 = g_csrc[e + 2], s3 = g_csrc[e + 3];
        unsigned w0 = __ldg(&yb[(size_t)s0 * 32 + lane]);
        unsigned w1 = __ldg(&yb[(size_t)s1 * 32 + lane]);
        unsigned w2 = __ldg(&yb[(size_t)s2 * 32 + lane]);
        unsigned w3 = __ldg(&yb[(size_t)s3 * 32 + lane]);
        ax += (BF2X(w0) + BF2X(w1)) + (BF2X(w2) + BF2X(w3));
        ay += (BF2Y(w0) + BF2Y(w1)) + (BF2Y(w2) + BF2Y(w3));
    }
    for (; e < end; e++) {
        int s = g_csrc[e];
        unsigned w = __ldg(&yb[(size_t)s * 32 + lane]);
        ax += BF2X(w); ay += BF2Y(w);
    }
    float d = g_dinv[i];
    float2 bb = ((const float2*)b)[lane];
    float hx = fmaxf(fmaf(d, ax, bb.x), 0.f);
    float hy = fmaxf(fmaf(d, ay, bb.y), 0.f);
    float2 wo = ((const float2*)Wout)[lane];
    float s = hx * wo.x + hy * wo.y;
#pragma unroll
    for (int off = 16; off; off >>= 1) s += __shfl_xor_sync(0xffffffffu, s, off);
    if (lane == 0) {
        int g = load_id(batch, i, g_is64);
        if ((unsigned)g < NG) atomicAdd(&out[g], s * g_ginv[g]);
    }
}

extern "C" void kernel_launch(void* const* d_in, const int* in_sizes, int n_in,
                              void* d_out, int out_size) {
    const float* x     = (const float*)d_in[0];
    const void*  ei    = d_in[1];
    const void*  batch = d_in[2];
    const float* W1    = (const float*)d_in[3];
    const float* b1    = (const float*)d_in[4];
    const float* W2    = (const float*)d_in[5];
    const float* b2    = (const float*)d_in[6];
    const float* Wout  = (const float*)d_in[7];
    const float* bout  = (const float*)d_in[8];
    float*       out   = (float*)d_out;

    (void)in_sizes; (void)n_in; (void)out_size;

    k_init     <<<(NN + 255) / 256, 256>>>((const int*)ei, bout, out);
    k_degcnt   <<<(NE / 2 + 255) / 256, 256>>>(ei, batch);
    k_scan1    <<<(NN + 1023) / 1024, 1024>>>();
    k_scanapply<<<(NN + 255) / 256, 256>>>();
    k_csr      <<<(NE / 2 + 255) / 256, 256>>>(ei);

    // layer 1
    k_gemm     <<<(NN + 255) / 256, 256>>>(x, W1, 0);
    k_agg1     <<<(NN * 32 + 255) / 256, 256>>>(b1);
    // layer 2 (+ fused pool/head)
    k_gemm     <<<(NN + 255) / 256, 256>>>(x, W2, 1);
    k_agg2     <<<(NN * 32 + 255) / 256, 256>>>(b2, Wout, batch, out);
}